// round 7
// baseline (speedup 1.0000x reference)
#include <cuda_runtime.h>
#include <cstddef>

#define N_USER  100000
#define N_MOVIE 20000
#define D_IN    64
#define HID     128
#define OUT_D   64
#define NE      600000

// ---------------------------------------------------------------------------
// Scratch (zero-init __device__ array). Float offsets.
// ---------------------------------------------------------------------------
#define OFF_AGG1   0
#define OFF_AGG2   6400000
#define OFF_AGG3   7680000
#define OFF_DEGU   20480000
#define OFF_DEGM   20580000
#define ZERO_FLOATS 20600000
#define OFF_USERX  20600000
#define OFF_MOVIEX 33400000
#define SCRATCH_TOTAL 35960000

__device__ float g_scratch[SCRATCH_TOTAL];

__device__ __forceinline__ void red_add_v4(float* p, float4 v) {
    asm volatile("red.global.add.v4.f32 [%0], {%1, %2, %3, %4};"
                 :: "l"(p), "f"(v.x), "f"(v.y), "f"(v.z), "f"(v.w)
                 : "memory");
}

// Packed fp32x2 FMA (SASS FFMA2): d = a*b + d, two lanes per instruction.
__device__ __forceinline__ void ffma2(unsigned long long& d,
                                      unsigned long long a,
                                      unsigned long long b) {
    asm("fma.rn.f32x2 %0, %1, %2, %0;" : "+l"(d) : "l"(a), "l"(b));
}
__device__ __forceinline__ unsigned long long bcast2(float a) {
    unsigned long long r;
    asm("mov.b64 %0, {%1, %1};" : "=l"(r) : "f"(a));
    return r;
}
__device__ __forceinline__ float2 unpack2(unsigned long long v) {
    float2 f;
    asm("mov.b64 {%0, %1}, %2;" : "=f"(f.x), "=f"(f.y) : "l"(v));
    return f;
}

// ---------------------------------------------------------------------------
// Fused conv1+conv2 scatter (both 64-wide, same edge list).
// ---------------------------------------------------------------------------
__global__ __launch_bounds__(256)
void scatter12_kernel(const float4* __restrict__ x_movie,
                      const float4* __restrict__ x_user,
                      const int* __restrict__ edge_movie,
                      const int* __restrict__ edge_user,
                      float* __restrict__ agg1,
                      float* __restrict__ agg2,
                      float* __restrict__ degU,
                      float* __restrict__ degM)
{
    int t = blockIdx.x * 256 + threadIdx.x;
    int e = t >> 4;
    if (e >= NE) return;
    int c = t & 15;
    int s = __ldg(&edge_movie[e]);
    int d = __ldg(&edge_user[e]);
    float4 vm = __ldg(&x_movie[s * 16 + c]);
    red_add_v4(agg1 + (d * 16 + c) * 4, vm);
    float4 vu = __ldg(&x_user[d * 16 + c]);
    red_add_v4(agg2 + (s * 16 + c) * 4, vu);
    if (c == 0) {
        atomicAdd(degU + d, 1.0f);
        atomicAdd(degM + s, 1.0f);
    }
}

__global__ __launch_bounds__(256)
void scatter3_kernel(const float4* __restrict__ xsrc,
                     const int* __restrict__ edge_movie,
                     const int* __restrict__ edge_user,
                     float* __restrict__ agg3)
{
    int t = blockIdx.x * 256 + threadIdx.x;
    int e = t >> 5;
    if (e >= NE) return;
    int c = t & 31;
    int s = __ldg(&edge_movie[e]);
    int d = __ldg(&edge_user[e]);
    float4 v = __ldg(&xsrc[s * 32 + c]);
    red_add_v4(agg3 + (d * 32 + c) * 4, v);
}

// ---------------------------------------------------------------------------
// Node-update with packed f32x2 FMA.
//   h = relu((agg/deg)@Wl + x@Wr + b); optional hidOut=h;
//   FUSE: linOut = h@Wlin + blin.
// TM=64 rows/block, 256 threads.
// GEMM1 tile: 2 rows x 16 cols  (rg=tid>>3; cg=tid&7 -> cols cg*16)
// GEMM2 tile: 2 rows x 8 cols
// sIn rows padded (+4 floats); sH overlays sIn after GEMM1.
// ---------------------------------------------------------------------------
template<int K, bool FUSE, bool WRITE_HID>
__global__ __launch_bounds__(256)
void update_kernel(const float* __restrict__ agg,
                   const float* __restrict__ deg,
                   const float* __restrict__ x,
                   const float* __restrict__ Wl,
                   const float* __restrict__ Wr,
                   const float* __restrict__ bias,
                   const float* __restrict__ Wlin,
                   const float* __restrict__ blin,
                   float* __restrict__ hidOut,
                   float* __restrict__ linOut,
                   int nRows)
{
    constexpr int TM = 64;
    constexpr int K2 = 2 * K;
    constexpr int VR = K / 4;
    constexpr int VK2 = K2 / 4;
    constexpr int SIN_ST = K2 + 4;
    constexpr int SH_ST  = HID + 4;
    extern __shared__ float smem[];
    float* sW    = smem;                  // [K2][HID]
    float* sIn   = sW + K2 * HID;         // [TM][SIN_ST], overlaid by sH [TM][SH_ST]
    float* sWlin = sIn + TM * SIN_ST;     // [HID][OUT_D] (FUSE only)
    float* sH    = sIn;

    const int tid = threadIdx.x;
    const int rowBase = blockIdx.x * TM;
    int nValid = nRows - rowBase;
    if (nValid > TM) nValid = TM;

    // --- stage weights: sW[0..K)=Wl, sW[K..2K)=Wr
    {
        const float4* Wl4 = (const float4*)Wl;
        const float4* Wr4 = (const float4*)Wr;
        float4* sW4 = (float4*)sW;
        const int nv = K * (HID / 4);
        for (int i = tid; i < nv; i += 256) { sW4[i] = Wl4[i]; sW4[nv + i] = Wr4[i]; }
    }
    if (FUSE) {
        const float4* Wlin4 = (const float4*)Wlin;
        float4* s4 = (float4*)sWlin;
        for (int i = tid; i < HID * (OUT_D / 4); i += 256) s4[i] = Wlin4[i];
    }
    // --- stage inputs: sIn[r][0..K)=agg/deg, sIn[r][K..2K)=x
    {
        const float4* agg4 = (const float4*)agg;
        const float4* x4   = (const float4*)x;
        for (int i = tid; i < TM * VR; i += 256) {
            int r = i / VR, j = i % VR;
            int row = rowBase + r;
            float4 a, xv;
            if (r < nValid) {
                float inv = 1.0f / fmaxf(__ldg(&deg[row]), 1.0f);
                a = agg4[(size_t)row * VR + j];
                a.x *= inv; a.y *= inv; a.z *= inv; a.w *= inv;
                xv = x4[(size_t)row * VR + j];
            } else {
                a = make_float4(0.f, 0.f, 0.f, 0.f); xv = a;
            }
            float4* sRow = (float4*)(sIn + r * SIN_ST);
            sRow[j]      = a;
            sRow[VR + j] = xv;
        }
    }
    __syncthreads();

    // --- GEMM1: [TM x K2] @ [K2 x HID], 2 rows x 16 cols per thread, f32x2
    const int rg = tid >> 3;   // 0..31 -> rows rg*2, rg*2+1
    const int cg = tid & 7;    // cols cg*16 .. +15 (8 pairs)
    unsigned long long acc[2][8];
    #pragma unroll
    for (int r = 0; r < 2; r++)
        #pragma unroll
        for (int p = 0; p < 8; p++) acc[r][p] = 0ULL;

    const float4* in0 = (const float4*)(sIn + (rg * 2 + 0) * SIN_ST);
    const float4* in1 = (const float4*)(sIn + (rg * 2 + 1) * SIN_ST);
    const float* wp = sW + cg * 16;

    #pragma unroll 4
    for (int k4 = 0; k4 < VK2; k4++) {
        float4 a0 = in0[k4];
        float4 a1 = in1[k4];
        float as0[4] = {a0.x, a0.y, a0.z, a0.w};
        float as1[4] = {a1.x, a1.y, a1.z, a1.w};
        #pragma unroll
        for (int u = 0; u < 4; u++) {
            const ulonglong2* wrow = (const ulonglong2*)(wp + (k4 * 4 + u) * HID);
            ulonglong2 wa = wrow[0], wb = wrow[1], wc = wrow[2], wd = wrow[3];
            unsigned long long w[8] = {wa.x, wa.y, wb.x, wb.y, wc.x, wc.y, wd.x, wd.y};
            unsigned long long b0 = bcast2(as0[u]);
            unsigned long long b1 = bcast2(as1[u]);
            #pragma unroll
            for (int p = 0; p < 8; p++) {
                ffma2(acc[0][p], b0, w[p]);
                ffma2(acc[1][p], b1, w[p]);
            }
        }
    }

    // bias + relu -> fOut[2][16]
    float fOut[2][16];
    {
        const float* bp = bias + cg * 16;
        float bj[16];
        #pragma unroll
        for (int j = 0; j < 16; j++) bj[j] = __ldg(bp + j);
        #pragma unroll
        for (int r = 0; r < 2; r++)
            #pragma unroll
            for (int p = 0; p < 8; p++) {
                float2 f = unpack2(acc[r][p]);
                fOut[r][2*p]   = fmaxf(f.x + bj[2*p],   0.f);
                fOut[r][2*p+1] = fmaxf(f.y + bj[2*p+1], 0.f);
            }
    }

    if (WRITE_HID) {
        #pragma unroll
        for (int r = 0; r < 2; r++) {
            int lr = rg * 2 + r;
            if (lr < nValid) {
                float* h = hidOut + (size_t)(rowBase + lr) * HID + cg * 16;
                #pragma unroll
                for (int q = 0; q < 4; q++)
                    ((float4*)h)[q] = make_float4(fOut[r][4*q], fOut[r][4*q+1],
                                                  fOut[r][4*q+2], fOut[r][4*q+3]);
            }
        }
    }

    if (FUSE) {
        __syncthreads();   // finish all GEMM1 reads of sIn before overlay
        #pragma unroll
        for (int r = 0; r < 2; r++) {
            float* s = sH + (rg * 2 + r) * SH_ST + cg * 16;
            #pragma unroll
            for (int q = 0; q < 4; q++)
                ((float4*)s)[q] = make_float4(fOut[r][4*q], fOut[r][4*q+1],
                                              fOut[r][4*q+2], fOut[r][4*q+3]);
        }
        __syncthreads();

        // --- GEMM2: [TM x HID] @ [HID x OUT_D], 2 rows x 8 cols, f32x2
        unsigned long long a2[2][4];
        #pragma unroll
        for (int r = 0; r < 2; r++)
            #pragma unroll
            for (int p = 0; p < 4; p++) a2[r][p] = 0ULL;

        const float4* h0 = (const float4*)(sH + (rg * 2 + 0) * SH_ST);
        const float4* h1 = (const float4*)(sH + (rg * 2 + 1) * SH_ST);
        const float* wl2 = sWlin + cg * 8;

        #pragma unroll 4
        for (int k4 = 0; k4 < HID / 4; k4++) {
            float4 v0 = h0[k4];
            float4 v1 = h1[k4];
            float hs0[4] = {v0.x, v0.y, v0.z, v0.w};
            float hs1[4] = {v1.x, v1.y, v1.z, v1.w};
            #pragma unroll
            for (int u = 0; u < 4; u++) {
                const ulonglong2* wrow = (const ulonglong2*)(wl2 + (k4 * 4 + u) * OUT_D);
                ulonglong2 wa = wrow[0], wb = wrow[1];
                unsigned long long w[4] = {wa.x, wa.y, wb.x, wb.y};
                unsigned long long b0 = bcast2(hs0[u]);
                unsigned long long b1 = bcast2(hs1[u]);
                #pragma unroll
                for (int p = 0; p < 4; p++) {
                    ffma2(a2[0][p], b0, w[p]);
                    ffma2(a2[1][p], b1, w[p]);
                }
            }
        }
        float bl[8];
        #pragma unroll
        for (int c = 0; c < 8; c++) bl[c] = __ldg(blin + cg * 8 + c);
        #pragma unroll
        for (int r = 0; r < 2; r++) {
            int lr = rg * 2 + r;
            if (lr < nValid) {
                float o[8];
                #pragma unroll
                for (int p = 0; p < 4; p++) {
                    float2 f = unpack2(a2[r][p]);
                    o[2*p]   = f.x + bl[2*p];
                    o[2*p+1] = f.y + bl[2*p+1];
                }
                float* op = linOut + (size_t)(rowBase + lr) * OUT_D + cg * 8;
                ((float4*)op)[0] = make_float4(o[0], o[1], o[2], o[3]);
                ((float4*)op)[1] = make_float4(o[4], o[5], o[6], o[7]);
            }
        }
    }
}

// ---------------------------------------------------------------------------
// Host launcher with fork-join: conv1-update overlaps conv2-update+scatter3.
// ---------------------------------------------------------------------------
extern "C" void kernel_launch(void* const* d_in, const int* in_sizes, int n_in,
                              void* d_out, int out_size)
{
    const float* x_user    = (const float*)d_in[0];
    const float* x_movie   = (const float*)d_in[1];
    const int*   edge_user = (const int*)d_in[2];
    const int*   edge_movie= (const int*)d_in[3];
    const float* W1l = (const float*)d_in[4];
    const float* W1r = (const float*)d_in[5];
    const float* b1  = (const float*)d_in[6];
    const float* W2l = (const float*)d_in[7];
    const float* W2r = (const float*)d_in[8];
    const float* b2  = (const float*)d_in[9];
    const float* W3l = (const float*)d_in[10];
    const float* W3r = (const float*)d_in[11];
    const float* b3  = (const float*)d_in[12];
    const float* Wlin1 = (const float*)d_in[13];
    const float* blin1 = (const float*)d_in[14];
    const float* Wlin2 = (const float*)d_in[15];
    const float* blin2 = (const float*)d_in[16];

    float* out = (float*)d_out;
    float* out_user  = out;
    float* out_movie = out + (size_t)N_USER * OUT_D;

    float* scratch = nullptr;
    cudaGetSymbolAddress((void**)&scratch, g_scratch);
    float* agg1   = scratch + OFF_AGG1;
    float* agg2   = scratch + OFF_AGG2;
    float* agg3   = scratch + OFF_AGG3;
    float* degU   = scratch + OFF_DEGU;
    float* degM   = scratch + OFF_DEGM;
    float* userx  = scratch + OFF_USERX;
    float* moviex = scratch + OFF_MOVIEX;

    // dynamic smem (bytes), padded sIn rows:
    const int SM_K64   = (2*64*HID  + 64*(2*64 + 4)) * 4;               // 99328
    const int SM_K64F  = (2*64*HID  + 64*(2*64 + 4) + HID*OUT_D) * 4;   // 132096
    const int SM_K128F = (2*128*HID + 64*(2*128 + 4) + HID*OUT_D) * 4;  // 230400

    cudaFuncSetAttribute(update_kernel<64, false, true>,
                         cudaFuncAttributeMaxDynamicSharedMemorySize, SM_K64);
    cudaFuncSetAttribute(update_kernel<64, true, true>,
                         cudaFuncAttributeMaxDynamicSharedMemorySize, SM_K64F);
    cudaFuncSetAttribute(update_kernel<128, true, false>,
                         cudaFuncAttributeMaxDynamicSharedMemorySize, SM_K128F);

    static cudaStream_t s2 = nullptr;
    static cudaEvent_t evFork = nullptr, evJoin = nullptr;
    if (!s2) {
        cudaStreamCreateWithFlags(&s2, cudaStreamNonBlocking);
        cudaEventCreateWithFlags(&evFork, cudaEventDisableTiming);
        cudaEventCreateWithFlags(&evJoin, cudaEventDisableTiming);
    }

    cudaMemsetAsync(scratch, 0, (size_t)ZERO_FLOATS * sizeof(float), 0);

    // fused conv1+conv2 scatter + degree counters
    scatter12_kernel<<<(NE * 16) / 256, 256>>>(
        (const float4*)x_movie, (const float4*)x_user,
        edge_movie, edge_user, agg1, agg2, degU, degM);

    const int GU = (N_USER  + 63) / 64;   // 1563
    const int GM = (N_MOVIE + 63) / 64;   // 313

    // fork: conv1 update (user) on s2, overlapping conv2-update + scatter3
    cudaEventRecord(evFork, 0);
    cudaStreamWaitEvent(s2, evFork, 0);
    update_kernel<64, false, true><<<GU, 256, SM_K64, s2>>>(
        agg1, degU, x_user, W1l, W1r, b1, nullptr, nullptr, userx, nullptr, N_USER);
    cudaEventRecord(evJoin, s2);

    // main stream: conv2 update (movie) -> moviex + fused out_movie
    update_kernel<64, true, true><<<GM, 256, SM_K64F>>>(
        agg2, degM, x_movie, W2l, W2r, b2, Wlin2, blin2, moviex, out_movie, N_MOVIE);

    // conv3 scatter: moviex -> agg3
    scatter3_kernel<<<(NE * 32) / 256, 256>>>(
        (const float4*)moviex, edge_movie, edge_user, agg3);

    // join: conv3 needs userx from s2
    cudaStreamWaitEvent(0, evJoin, 0);

    // conv3 update (user) + fused lin1 -> out_user
    update_kernel<128, true, false><<<GU, 256, SM_K128F>>>(
        agg3, degU, userx, W3l, W3r, b3, Wlin1, blin1, nullptr, out_user, N_USER);
}

// round 10
// speedup vs baseline: 2.2608x; 2.2608x over previous
#include <cuda_runtime.h>
#include <cstddef>

#define N_USER  100000
#define N_MOVIE 20000
#define D_IN    64
#define HID     128
#define OUT_D   64
#define NE      600000

// ---------------------------------------------------------------------------
// Scratch (zero-init __device__ array). Float offsets.
// ---------------------------------------------------------------------------
#define OFF_AGG1   0
#define OFF_AGG2   6400000
#define OFF_AGG3   7680000
#define OFF_DEGU   20480000
#define OFF_DEGM   20580000
#define ZERO_FLOATS 20600000
#define OFF_USERX  20600000
#define OFF_MOVIEX 33400000
#define SCRATCH_TOTAL 35960000

__device__ float g_scratch[SCRATCH_TOTAL];

__device__ __forceinline__ void red_add_v4(float* p, float4 v) {
    asm volatile("red.global.add.v4.f32 [%0], {%1, %2, %3, %4};"
                 :: "l"(p), "f"(v.x), "f"(v.y), "f"(v.z), "f"(v.w)
                 : "memory");
}

// ---------------------------------------------------------------------------
// Fused conv1+conv2 scatter (both 64-wide, same edge list).
// ---------------------------------------------------------------------------
__global__ __launch_bounds__(256)
void scatter12_kernel(const float4* __restrict__ x_movie,
                      const float4* __restrict__ x_user,
                      const int* __restrict__ edge_movie,
                      const int* __restrict__ edge_user,
                      float* __restrict__ agg1,
                      float* __restrict__ agg2,
                      float* __restrict__ degU,
                      float* __restrict__ degM)
{
    int t = blockIdx.x * 256 + threadIdx.x;
    int e = t >> 4;
    if (e >= NE) return;
    int c = t & 15;
    int s = __ldg(&edge_movie[e]);
    int d = __ldg(&edge_user[e]);
    float4 vm = __ldg(&x_movie[s * 16 + c]);
    red_add_v4(agg1 + (d * 16 + c) * 4, vm);
    float4 vu = __ldg(&x_user[d * 16 + c]);
    red_add_v4(agg2 + (s * 16 + c) * 4, vu);
    if (c == 0) {
        atomicAdd(degU + d, 1.0f);
        atomicAdd(degM + s, 1.0f);
    }
}

__global__ __launch_bounds__(256)
void scatter3_kernel(const float4* __restrict__ xsrc,
                     const int* __restrict__ edge_movie,
                     const int* __restrict__ edge_user,
                     float* __restrict__ agg3)
{
    int t = blockIdx.x * 256 + threadIdx.x;
    int e = t >> 5;
    if (e >= NE) return;
    int c = t & 31;
    int s = __ldg(&edge_movie[e]);
    int d = __ldg(&edge_user[e]);
    float4 v = __ldg(&xsrc[s * 32 + c]);
    red_add_v4(agg3 + (d * 32 + c) * 4, v);
}

// ---------------------------------------------------------------------------
// Node-update (R3-verified config): scalar fp32 FFMA, 4x8 register blocking.
//   h = relu((agg/deg)@Wl + x@Wr + b); optional hidOut=h;
//   FUSE: linOut = h@Wlin + blin.
// TM=64 rows/block, 256 threads. sH overlays sIn after GEMM1.
// ---------------------------------------------------------------------------
template<int K, bool FUSE, bool WRITE_HID>
__global__ __launch_bounds__(256)
void update_kernel(const float* __restrict__ agg,
                   const float* __restrict__ deg,
                   const float* __restrict__ x,
                   const float* __restrict__ Wl,
                   const float* __restrict__ Wr,
                   const float* __restrict__ bias,
                   const float* __restrict__ Wlin,
                   const float* __restrict__ blin,
                   float* __restrict__ hidOut,
                   float* __restrict__ linOut,
                   int nRows)
{
    constexpr int TM = 64;
    constexpr int K2 = 2 * K;
    constexpr int VR = K / 4;     // float4 per half input row
    constexpr int VK2 = K2 / 4;   // float4 per full input row
    extern __shared__ float smem[];
    float* sW    = smem;                 // [K2][HID]
    float* sIn   = sW + K2 * HID;        // [TM][K2], reused as sH [TM][HID]
    float* sWlin = sIn + TM * K2;        // [HID][OUT_D] (FUSE only)
    float* sH    = sIn;                  // overlay

    const int tid = threadIdx.x;
    const int rowBase = blockIdx.x * TM;
    int nValid = nRows - rowBase;
    if (nValid > TM) nValid = TM;

    // --- stage weights: sW[0..K) = Wl, sW[K..2K) = Wr
    {
        const float4* Wl4 = (const float4*)Wl;
        const float4* Wr4 = (const float4*)Wr;
        float4* sW4 = (float4*)sW;
        const int nv = K * (HID / 4);
        for (int i = tid; i < nv; i += 256) { sW4[i] = Wl4[i]; sW4[nv + i] = Wr4[i]; }
    }
    if (FUSE) {
        const float4* Wlin4 = (const float4*)Wlin;
        float4* s4 = (float4*)sWlin;
        for (int i = tid; i < HID * (OUT_D / 4); i += 256) s4[i] = Wlin4[i];
    }
    // --- stage inputs: sIn[r][0..K)=agg/deg, sIn[r][K..2K)=x
    {
        const float4* agg4 = (const float4*)agg;
        const float4* x4   = (const float4*)x;
        for (int i = tid; i < TM * VR; i += 256) {
            int r = i / VR, j = i % VR;
            int row = rowBase + r;
            float4 a, xv;
            if (r < nValid) {
                float inv = 1.0f / fmaxf(__ldg(&deg[row]), 1.0f);
                a = agg4[(size_t)row * VR + j];
                a.x *= inv; a.y *= inv; a.z *= inv; a.w *= inv;
                xv = x4[(size_t)row * VR + j];
            } else {
                a = make_float4(0.f, 0.f, 0.f, 0.f); xv = a;
            }
            float4* sRow = (float4*)(sIn + r * K2);
            sRow[j]      = a;
            sRow[VR + j] = xv;
        }
    }
    __syncthreads();

    // --- GEMM1: [TM x K2] @ [K2 x HID], 4x8 per thread
    const int rg = tid >> 4;   // 0..15
    const int cg = tid & 15;   // 0..15
    float acc[4][8];
    #pragma unroll
    for (int r = 0; r < 4; r++)
        #pragma unroll
        for (int j = 0; j < 8; j++) acc[r][j] = 0.f;

    const float* wp = sW + cg * 8;
    const float4* in4[4];
    #pragma unroll
    for (int r = 0; r < 4; r++) in4[r] = (const float4*)(sIn + (rg * 4 + r) * K2);

    #pragma unroll 2
    for (int k4 = 0; k4 < VK2; k4++) {
        float4 av[4];
        #pragma unroll
        for (int r = 0; r < 4; r++) av[r] = in4[r][k4];
        float as[4][4];
        #pragma unroll
        for (int r = 0; r < 4; r++) {
            as[r][0] = av[r].x; as[r][1] = av[r].y; as[r][2] = av[r].z; as[r][3] = av[r].w;
        }
        #pragma unroll
        for (int u = 0; u < 4; u++) {
            const float4* wrow = (const float4*)(wp + (k4 * 4 + u) * HID);
            float4 w0 = wrow[0];
            float4 w1 = wrow[1];
            float w[8] = {w0.x, w0.y, w0.z, w0.w, w1.x, w1.y, w1.z, w1.w};
            #pragma unroll
            for (int r = 0; r < 4; r++) {
                float a = as[r][u];
                #pragma unroll
                for (int j = 0; j < 8; j++) acc[r][j] = fmaf(a, w[j], acc[r][j]);
            }
        }
    }

    // bias + relu
    {
        const float* bp = bias + cg * 8;
        float bj[8];
        #pragma unroll
        for (int j = 0; j < 8; j++) bj[j] = __ldg(bp + j);
        #pragma unroll
        for (int r = 0; r < 4; r++)
            #pragma unroll
            for (int j = 0; j < 8; j++) acc[r][j] = fmaxf(acc[r][j] + bj[j], 0.f);
    }

    if (WRITE_HID) {
        #pragma unroll
        for (int r = 0; r < 4; r++) {
            int row = rowBase + rg * 4 + r;
            if (rg * 4 + r < nValid) {
                float* h = hidOut + (size_t)row * HID + cg * 8;
                ((float4*)h)[0] = make_float4(acc[r][0], acc[r][1], acc[r][2], acc[r][3]);
                ((float4*)h)[1] = make_float4(acc[r][4], acc[r][5], acc[r][6], acc[r][7]);
            }
        }
    }

    if (FUSE) {
        __syncthreads();   // all GEMM1 reads of sIn done before overlay write
        #pragma unroll
        for (int r = 0; r < 4; r++) {
            float* s = sH + (rg * 4 + r) * HID + cg * 8;
            ((float4*)s)[0] = make_float4(acc[r][0], acc[r][1], acc[r][2], acc[r][3]);
            ((float4*)s)[1] = make_float4(acc[r][4], acc[r][5], acc[r][6], acc[r][7]);
        }
        __syncthreads();

        // --- GEMM2: [TM x HID] @ [HID x OUT_D], 4x4 per thread
        const int rg2 = tid >> 4;  // rows rg2*4..+3
        const int cg2 = tid & 15;  // cols cg2*4..+3
        float a2[4][4];
        #pragma unroll
        for (int r = 0; r < 4; r++)
            #pragma unroll
            for (int c = 0; c < 4; c++) a2[r][c] = 0.f;

        const float4* h4[4];
        #pragma unroll
        for (int r = 0; r < 4; r++) h4[r] = (const float4*)(sH + (rg2 * 4 + r) * HID);
        const float* wl2 = sWlin + cg2 * 4;

        #pragma unroll 2
        for (int k4 = 0; k4 < HID / 4; k4++) {
            float4 hv[4];
            #pragma unroll
            for (int r = 0; r < 4; r++) hv[r] = h4[r][k4];
            float hs[4][4];
            #pragma unroll
            for (int r = 0; r < 4; r++) {
                hs[r][0] = hv[r].x; hs[r][1] = hv[r].y; hs[r][2] = hv[r].z; hs[r][3] = hv[r].w;
            }
            #pragma unroll
            for (int u = 0; u < 4; u++) {
                float4 w4 = *(const float4*)(wl2 + (k4 * 4 + u) * OUT_D);
                float w[4] = {w4.x, w4.y, w4.z, w4.w};
                #pragma unroll
                for (int r = 0; r < 4; r++) {
                    float h = hs[r][u];
                    #pragma unroll
                    for (int c = 0; c < 4; c++) a2[r][c] = fmaf(h, w[c], a2[r][c]);
                }
            }
        }
        float bl[4];
        #pragma unroll
        for (int c = 0; c < 4; c++) bl[c] = __ldg(blin + cg2 * 4 + c);
        #pragma unroll
        for (int r = 0; r < 4; r++) {
            int row = rowBase + rg2 * 4 + r;
            if (rg2 * 4 + r < nValid) {
                float* op = linOut + (size_t)row * OUT_D + cg2 * 4;
                *(float4*)op = make_float4(a2[r][0] + bl[0], a2[r][1] + bl[1],
                                           a2[r][2] + bl[2], a2[r][3] + bl[3]);
            }
        }
    }
}

// ---------------------------------------------------------------------------
// Host launcher with fork-join: conv1-update overlaps conv2-update+scatter3.
// ---------------------------------------------------------------------------
extern "C" void kernel_launch(void* const* d_in, const int* in_sizes, int n_in,
                              void* d_out, int out_size)
{
    const float* x_user    = (const float*)d_in[0];
    const float* x_movie   = (const float*)d_in[1];
    const int*   edge_user = (const int*)d_in[2];
    const int*   edge_movie= (const int*)d_in[3];
    const float* W1l = (const float*)d_in[4];
    const float* W1r = (const float*)d_in[5];
    const float* b1  = (const float*)d_in[6];
    const float* W2l = (const float*)d_in[7];
    const float* W2r = (const float*)d_in[8];
    const float* b2  = (const float*)d_in[9];
    const float* W3l = (const float*)d_in[10];
    const float* W3r = (const float*)d_in[11];
    const float* b3  = (const float*)d_in[12];
    const float* Wlin1 = (const float*)d_in[13];
    const float* blin1 = (const float*)d_in[14];
    const float* Wlin2 = (const float*)d_in[15];
    const float* blin2 = (const float*)d_in[16];

    float* out = (float*)d_out;
    float* out_user  = out;
    float* out_movie = out + (size_t)N_USER * OUT_D;

    float* scratch = nullptr;
    cudaGetSymbolAddress((void**)&scratch, g_scratch);
    float* agg1   = scratch + OFF_AGG1;
    float* agg2   = scratch + OFF_AGG2;
    float* agg3   = scratch + OFF_AGG3;
    float* degU   = scratch + OFF_DEGU;
    float* degM   = scratch + OFF_DEGM;
    float* userx  = scratch + OFF_USERX;
    float* moviex = scratch + OFF_MOVIEX;

    // dynamic smem (bytes), TM=64 (R3-verified sizes):
    const int SM_K64   = (2*64*HID  + 64*2*64) * 4;                 // 98304
    const int SM_K64F  = (2*64*HID  + 64*2*64  + HID*OUT_D) * 4;    // 131072
    const int SM_K128F = (2*128*HID + 64*2*128 + HID*OUT_D) * 4;    // 229376

    cudaFuncSetAttribute(update_kernel<64, false, true>,
                         cudaFuncAttributeMaxDynamicSharedMemorySize, SM_K64);
    cudaFuncSetAttribute(update_kernel<64, true, true>,
                         cudaFuncAttributeMaxDynamicSharedMemorySize, SM_K64F);
    cudaFuncSetAttribute(update_kernel<128, true, false>,
                         cudaFuncAttributeMaxDynamicSharedMemorySize, SM_K128F);

    static cudaStream_t s2 = nullptr;
    static cudaEvent_t evFork = nullptr, evJoin = nullptr;
    if (!s2) {
        cudaStreamCreateWithFlags(&s2, cudaStreamNonBlocking);
        cudaEventCreateWithFlags(&evFork, cudaEventDisableTiming);
        cudaEventCreateWithFlags(&evJoin, cudaEventDisableTiming);
    }

    cudaMemsetAsync(scratch, 0, (size_t)ZERO_FLOATS * sizeof(float), 0);

    // fused conv1+conv2 scatter + degree counters
    scatter12_kernel<<<(NE * 16) / 256, 256>>>(
        (const float4*)x_movie, (const float4*)x_user,
        edge_movie, edge_user, agg1, agg2, degU, degM);

    const int GU = (N_USER  + 63) / 64;   // 1563
    const int GM = (N_MOVIE + 63) / 64;   // 313

    // fork: conv1 update (user) on s2, overlapping conv2-update + scatter3
    cudaEventRecord(evFork, 0);
    cudaStreamWaitEvent(s2, evFork, 0);
    update_kernel<64, false, true><<<GU, 256, SM_K64, s2>>>(
        agg1, degU, x_user, W1l, W1r, b1, nullptr, nullptr, userx, nullptr, N_USER);
    cudaEventRecord(evJoin, s2);

    // main stream: conv2 update (movie) -> moviex + fused out_movie
    update_kernel<64, true, true><<<GM, 256, SM_K64F>>>(
        agg2, degM, x_movie, W2l, W2r, b2, Wlin2, blin2, moviex, out_movie, N_MOVIE);

    // conv3 scatter: moviex -> agg3
    scatter3_kernel<<<(NE * 32) / 256, 256>>>(
        (const float4*)moviex, edge_movie, edge_user, agg3);

    // join: conv3 needs userx from s2
    cudaStreamWaitEvent(0, evJoin, 0);

    // conv3 update (user) + fused lin1 -> out_user
    update_kernel<128, true, false><<<GU, 256, SM_K128F>>>(
        agg3, degU, userx, W3l, W3r, b3, Wlin1, blin1, nullptr, out_user, N_USER);
}

// round 13
// speedup vs baseline: 2.5847x; 1.1433x over previous
#include <cuda_runtime.h>
#include <cuda_bf16.h>
#include <cstdint>
#include <cstddef>

#define N_USER  100000
#define N_MOVIE 20000
#define D_IN    64
#define HID     128
#define OUT_D   64
#define NE      600000

// ---------------------------------------------------------------------------
// Scratch (zero-init __device__ array). Float offsets.
// ---------------------------------------------------------------------------
#define OFF_AGG1   0
#define OFF_AGG2   6400000
#define OFF_AGG3   7680000
#define OFF_DEGU   20480000
#define OFF_DEGM   20580000
#define ZERO_FLOATS 20600000
#define OFF_USERX  20600000
#define OFF_MOVIEX 33400000
#define SCRATCH_TOTAL 35960000

__device__ float g_scratch[SCRATCH_TOTAL];

__device__ __forceinline__ void red_add_v4(float* p, float4 v) {
    asm volatile("red.global.add.v4.f32 [%0], {%1, %2, %3, %4};"
                 :: "l"(p), "f"(v.x), "f"(v.y), "f"(v.z), "f"(v.w)
                 : "memory");
}

__device__ __forceinline__ uint32_t smem_to_u32(const void* smem_ptr) {
    uint32_t addr;
    asm("{ .reg .u64 tmp; cvta.to.shared.u64 tmp, %1; cvt.u32.u64 %0, tmp; }"
        : "=r"(addr) : "l"(smem_ptr));
    return addr;
}

// ldmatrix / mma.sync helpers (family-common PTX, valid on target sm_103)
__device__ __forceinline__ void ldsm_x4(uint32_t* r, uint32_t addr) {
    asm volatile("ldmatrix.sync.aligned.m8n8.x4.shared.b16 {%0,%1,%2,%3}, [%4];"
                 : "=r"(r[0]), "=r"(r[1]), "=r"(r[2]), "=r"(r[3]) : "r"(addr));
}
__device__ __forceinline__ void ldsm_x2(uint32_t* r, uint32_t addr) {
    asm volatile("ldmatrix.sync.aligned.m8n8.x2.shared.b16 {%0,%1}, [%2];"
                 : "=r"(r[0]), "=r"(r[1]) : "r"(addr));
}
__device__ __forceinline__ void mma_bf16(float* c, const uint32_t* a, const uint32_t* b) {
    asm volatile(
        "mma.sync.aligned.m16n8k16.row.col.f32.bf16.bf16.f32 "
        "{%0,%1,%2,%3}, {%4,%5,%6,%7}, {%8,%9}, {%0,%1,%2,%3};"
        : "+f"(c[0]), "+f"(c[1]), "+f"(c[2]), "+f"(c[3])
        : "r"(a[0]), "r"(a[1]), "r"(a[2]), "r"(a[3]), "r"(b[0]), "r"(b[1]));
}
__device__ __forceinline__ uint32_t pack_bf16x2(__nv_bfloat16 lo16, __nv_bfloat16 hi16) {
    return ((uint32_t)__bfloat16_as_ushort(hi16) << 16) | (uint32_t)__bfloat16_as_ushort(lo16);
}

// ---------------------------------------------------------------------------
// Fused conv1+conv2 scatter (both 64-wide, same edge list).
// ---------------------------------------------------------------------------
__global__ __launch_bounds__(256)
void scatter12_kernel(const float4* __restrict__ x_movie,
                      const float4* __restrict__ x_user,
                      const int* __restrict__ edge_movie,
                      const int* __restrict__ edge_user,
                      float* __restrict__ agg1,
                      float* __restrict__ agg2,
                      float* __restrict__ degU,
                      float* __restrict__ degM)
{
    int t = blockIdx.x * 256 + threadIdx.x;
    int e = t >> 4;
    if (e >= NE) return;
    int c = t & 15;
    int s = __ldg(&edge_movie[e]);
    int d = __ldg(&edge_user[e]);
    float4 vm = __ldg(&x_movie[s * 16 + c]);
    red_add_v4(agg1 + (d * 16 + c) * 4, vm);
    float4 vu = __ldg(&x_user[d * 16 + c]);
    red_add_v4(agg2 + (s * 16 + c) * 4, vu);
    if (c == 0) {
        atomicAdd(degU + d, 1.0f);
        atomicAdd(degM + s, 1.0f);
    }
}

__global__ __launch_bounds__(256)
void scatter3_kernel(const float4* __restrict__ xsrc,
                     const int* __restrict__ edge_movie,
                     const int* __restrict__ edge_user,
                     float* __restrict__ agg3)
{
    int t = blockIdx.x * 256 + threadIdx.x;
    int e = t >> 5;
    if (e >= NE) return;
    int c = t & 31;
    int s = __ldg(&edge_movie[e]);
    int d = __ldg(&edge_user[e]);
    float4 v = __ldg(&xsrc[s * 32 + c]);
    red_add_v4(agg3 + (d * 32 + c) * 4, v);
}

// ---------------------------------------------------------------------------
// Node-update (R3-verified): scalar fp32 FFMA, 4x8 blocking. K=64 users only.
// ---------------------------------------------------------------------------
template<int K, bool FUSE, bool WRITE_HID>
__global__ __launch_bounds__(256)
void update_kernel(const float* __restrict__ agg,
                   const float* __restrict__ deg,
                   const float* __restrict__ x,
                   const float* __restrict__ Wl,
                   const float* __restrict__ Wr,
                   const float* __restrict__ bias,
                   const float* __restrict__ Wlin,
                   const float* __restrict__ blin,
                   float* __restrict__ hidOut,
                   float* __restrict__ linOut,
                   int nRows)
{
    constexpr int TM = 64;
    constexpr int K2 = 2 * K;
    constexpr int VR = K / 4;
    constexpr int VK2 = K2 / 4;
    extern __shared__ float smem[];
    float* sW    = smem;
    float* sIn   = sW + K2 * HID;
    float* sWlin = sIn + TM * K2;
    float* sH    = sIn;

    const int tid = threadIdx.x;
    const int rowBase = blockIdx.x * TM;
    int nValid = nRows - rowBase;
    if (nValid > TM) nValid = TM;

    {
        const float4* Wl4 = (const float4*)Wl;
        const float4* Wr4 = (const float4*)Wr;
        float4* sW4 = (float4*)sW;
        const int nv = K * (HID / 4);
        for (int i = tid; i < nv; i += 256) { sW4[i] = Wl4[i]; sW4[nv + i] = Wr4[i]; }
    }
    if (FUSE) {
        const float4* Wlin4 = (const float4*)Wlin;
        float4* s4 = (float4*)sWlin;
        for (int i = tid; i < HID * (OUT_D / 4); i += 256) s4[i] = Wlin4[i];
    }
    {
        const float4* agg4 = (const float4*)agg;
        const float4* x4   = (const float4*)x;
        for (int i = tid; i < TM * VR; i += 256) {
            int r = i / VR, j = i % VR;
            int row = rowBase + r;
            float4 a, xv;
            if (r < nValid) {
                float inv = 1.0f / fmaxf(__ldg(&deg[row]), 1.0f);
                a = agg4[(size_t)row * VR + j];
                a.x *= inv; a.y *= inv; a.z *= inv; a.w *= inv;
                xv = x4[(size_t)row * VR + j];
            } else {
                a = make_float4(0.f, 0.f, 0.f, 0.f); xv = a;
            }
            float4* sRow = (float4*)(sIn + r * K2);
            sRow[j]      = a;
            sRow[VR + j] = xv;
        }
    }
    __syncthreads();

    const int rg = tid >> 4;
    const int cg = tid & 15;
    float acc[4][8];
    #pragma unroll
    for (int r = 0; r < 4; r++)
        #pragma unroll
        for (int j = 0; j < 8; j++) acc[r][j] = 0.f;

    const float* wp = sW + cg * 8;
    const float4* in4[4];
    #pragma unroll
    for (int r = 0; r < 4; r++) in4[r] = (const float4*)(sIn + (rg * 4 + r) * K2);

    #pragma unroll 2
    for (int k4 = 0; k4 < VK2; k4++) {
        float4 av[4];
        #pragma unroll
        for (int r = 0; r < 4; r++) av[r] = in4[r][k4];
        float as[4][4];
        #pragma unroll
        for (int r = 0; r < 4; r++) {
            as[r][0] = av[r].x; as[r][1] = av[r].y; as[r][2] = av[r].z; as[r][3] = av[r].w;
        }
        #pragma unroll
        for (int u = 0; u < 4; u++) {
            const float4* wrow = (const float4*)(wp + (k4 * 4 + u) * HID);
            float4 w0 = wrow[0];
            float4 w1 = wrow[1];
            float w[8] = {w0.x, w0.y, w0.z, w0.w, w1.x, w1.y, w1.z, w1.w};
            #pragma unroll
            for (int r = 0; r < 4; r++) {
                float a = as[r][u];
                #pragma unroll
                for (int j = 0; j < 8; j++) acc[r][j] = fmaf(a, w[j], acc[r][j]);
            }
        }
    }

    {
        const float* bp = bias + cg * 8;
        float bj[8];
        #pragma unroll
        for (int j = 0; j < 8; j++) bj[j] = __ldg(bp + j);
        #pragma unroll
        for (int r = 0; r < 4; r++)
            #pragma unroll
            for (int j = 0; j < 8; j++) acc[r][j] = fmaxf(acc[r][j] + bj[j], 0.f);
    }

    if (WRITE_HID) {
        #pragma unroll
        for (int r = 0; r < 4; r++) {
            int row = rowBase + rg * 4 + r;
            if (rg * 4 + r < nValid) {
                float* h = hidOut + (size_t)row * HID + cg * 8;
                ((float4*)h)[0] = make_float4(acc[r][0], acc[r][1], acc[r][2], acc[r][3]);
                ((float4*)h)[1] = make_float4(acc[r][4], acc[r][5], acc[r][6], acc[r][7]);
            }
        }
    }

    if (FUSE) {
        __syncthreads();
        #pragma unroll
        for (int r = 0; r < 4; r++) {
            float* s = sH + (rg * 4 + r) * HID + cg * 8;
            ((float4*)s)[0] = make_float4(acc[r][0], acc[r][1], acc[r][2], acc[r][3]);
            ((float4*)s)[1] = make_float4(acc[r][4], acc[r][5], acc[r][6], acc[r][7]);
        }
        __syncthreads();

        const int rg2 = tid >> 4;
        const int cg2 = tid & 15;
        float a2[4][4];
        #pragma unroll
        for (int r = 0; r < 4; r++)
            #pragma unroll
            for (int c = 0; c < 4; c++) a2[r][c] = 0.f;

        const float4* h4[4];
        #pragma unroll
        for (int r = 0; r < 4; r++) h4[r] = (const float4*)(sH + (rg2 * 4 + r) * HID);
        const float* wl2 = sWlin + cg2 * 4;

        #pragma unroll 2
        for (int k4 = 0; k4 < HID / 4; k4++) {
            float4 hv[4];
            #pragma unroll
            for (int r = 0; r < 4; r++) hv[r] = h4[r][k4];
            float hs[4][4];
            #pragma unroll
            for (int r = 0; r < 4; r++) {
                hs[r][0] = hv[r].x; hs[r][1] = hv[r].y; hs[r][2] = hv[r].z; hs[r][3] = hv[r].w;
            }
            #pragma unroll
            for (int u = 0; u < 4; u++) {
                float4 w4 = *(const float4*)(wl2 + (k4 * 4 + u) * OUT_D);
                float w[4] = {w4.x, w4.y, w4.z, w4.w};
                #pragma unroll
                for (int r = 0; r < 4; r++) {
                    float h = hs[r][u];
                    #pragma unroll
                    for (int c = 0; c < 4; c++) a2[r][c] = fmaf(h, w[c], a2[r][c]);
                }
            }
        }
        float bl[4];
        #pragma unroll
        for (int c = 0; c < 4; c++) bl[c] = __ldg(blin + cg2 * 4 + c);
        #pragma unroll
        for (int r = 0; r < 4; r++) {
            int row = rowBase + rg2 * 4 + r;
            if (rg2 * 4 + r < nValid) {
                float* op = linOut + (size_t)row * OUT_D + cg2 * 4;
                *(float4*)op = make_float4(a2[r][0] + bl[0], a2[r][1] + bl[1],
                                           a2[r][2] + bl[2], a2[r][3] + bl[3]);
            }
        }
    }
}

// ---------------------------------------------------------------------------
// conv3 via mma.sync split-bf16 (family-common HMMA path; no tcgen05).
// Block: 256 threads (8 warps), tile M=128 x N=128, K=256 in two stages
//   (stage0: agg3/deg x W3l ; stage1: userx x W3r), accums persist.
// A hi/lo bf16 row-major [128][136]; B = W^T hi/lo [n=128][k=136].
// Per warp: rows 16w..16w+15, acc[16 n-tiles][4]. D = AhBh + AlBh + AhBl.
// Epilogue: bias+relu -> sH [128][132] f32 (overlays A) -> SIMT GEMM2 (lin1).
// SMEM bytes: A_hi 34816 | A_lo 34816 | B_hi 34816 | B_lo 34816 | Wlin 32768
// ---------------------------------------------------------------------------
#define C3_AH   0
#define C3_AL   34816
#define C3_BH   69632
#define C3_BL   104448
#define C3_WL   139264
#define C3_SMEM 172032

__global__ __launch_bounds__(256)
void conv3_mma_kernel(const float* __restrict__ agg3,
                      const float* __restrict__ deg,
                      const float* __restrict__ userx,
                      const float* __restrict__ Wl,
                      const float* __restrict__ Wr,
                      const float* __restrict__ bias,
                      const float* __restrict__ Wlin,
                      const float* __restrict__ blin,
                      float* __restrict__ linOut,
                      int nRows)
{
    extern __shared__ char smc[];
    const int tid = threadIdx.x;
    const int w = tid >> 5;
    const int lane = tid & 31;
    const int rowBase = blockIdx.x * 128;
    int nValid = nRows - rowBase;
    if (nValid > 128) nValid = 128;

    const uint32_t sbase = smem_to_u32(smc);

    // stage sWlin once
    {
        const float4* Wlin4 = (const float4*)Wlin;
        float4* s4 = (float4*)(smc + C3_WL);
        for (int i = tid; i < HID * (OUT_D / 4); i += 256) s4[i] = Wlin4[i];
    }

    float acc[16][4];
    #pragma unroll
    for (int nt = 0; nt < 16; nt++)
        #pragma unroll
        for (int c = 0; c < 4; c++) acc[nt][c] = 0.f;

    // per-thread ldmatrix source addresses (byte offsets added per kt/nt)
    const uint32_t aOff = ((uint32_t)(w * 16 + (lane & 15)) * 136u + (uint32_t)((lane >> 4) * 8)) * 2u;
    const uint32_t bOff = ((uint32_t)(lane & 7) * 136u + (uint32_t)(((lane >> 3) & 1) * 8)) * 2u;
    const uint32_t aHbase = sbase + C3_AH + aOff;
    const uint32_t aLbase = sbase + C3_AL + aOff;
    const uint32_t bHbase = sbase + C3_BH + bOff;
    const uint32_t bLbase = sbase + C3_BL + bOff;

    #pragma unroll 1
    for (int stage = 0; stage < 2; stage++) {
        // --- stage A: [128 rows][128 k] fp32 -> hi/lo bf16
        {
            const float4* agg4 = (const float4*)agg3;
            const float4* x4   = (const float4*)userx;
            uint32_t* aH = (uint32_t*)(smc + C3_AH);
            uint32_t* aL = (uint32_t*)(smc + C3_AL);
            for (int i = tid; i < 128 * 32; i += 256) {
                int r = i >> 5, j = i & 31;
                float4 v = make_float4(0.f, 0.f, 0.f, 0.f);
                if (r < nValid) {
                    size_t row = (size_t)(rowBase + r);
                    if (stage == 0) {
                        float inv = 1.0f / fmaxf(__ldg(&deg[row]), 1.0f);
                        v = agg4[row * 32 + j];
                        v.x *= inv; v.y *= inv; v.z *= inv; v.w *= inv;
                    } else {
                        v = x4[row * 32 + j];
                    }
                }
                __nv_bfloat16 h0 = __float2bfloat16(v.x), h1 = __float2bfloat16(v.y);
                __nv_bfloat16 h2 = __float2bfloat16(v.z), h3 = __float2bfloat16(v.w);
                __nv_bfloat16 l0 = __float2bfloat16(v.x - __bfloat162float(h0));
                __nv_bfloat16 l1 = __float2bfloat16(v.y - __bfloat162float(h1));
                __nv_bfloat16 l2 = __float2bfloat16(v.z - __bfloat162float(h2));
                __nv_bfloat16 l3 = __float2bfloat16(v.w - __bfloat162float(h3));
                int base = r * 68 + j * 2;   // row stride 136 bf16 = 68 b32
                aH[base]     = pack_bf16x2(h0, h1);
                aH[base + 1] = pack_bf16x2(h2, h3);
                aL[base]     = pack_bf16x2(l0, l1);
                aL[base + 1] = pack_bf16x2(l2, l3);
            }
        }
        // --- stage B: W[k][n] -> B[n][k] transposed, hi/lo bf16
        {
            const float* W = (stage == 0) ? Wl : Wr;
            __nv_bfloat16* bH = (__nv_bfloat16*)(smc + C3_BH);
            __nv_bfloat16* bL = (__nv_bfloat16*)(smc + C3_BL);
            for (int i = tid; i < 128 * 128; i += 256) {
                int k = i >> 7, n = i & 127;
                float wv = __ldg(&W[i]);
                __nv_bfloat16 h = __float2bfloat16(wv);
                __nv_bfloat16 l = __float2bfloat16(wv - __bfloat162float(h));
                bH[n * 136 + k] = h;
                bL[n * 136 + k] = l;
            }
        }
        __syncthreads();

        // --- MMA: 8 k-steps x 16 n-tiles x 3 products
        #pragma unroll 1
        for (int kt = 0; kt < 8; kt++) {
            uint32_t ah[4], al[4];
            ldsm_x4(ah, aHbase + (uint32_t)kt * 32u);
            ldsm_x4(al, aLbase + (uint32_t)kt * 32u);
            #pragma unroll
            for (int nt = 0; nt < 16; nt++) {
                uint32_t bh[2], bl[2];
                uint32_t off = (uint32_t)nt * 2176u + (uint32_t)kt * 32u;  // 8*136*2 = 2176
                ldsm_x2(bh, bHbase + off);
                ldsm_x2(bl, bLbase + off);
                mma_bf16(acc[nt], ah, bh);
                mma_bf16(acc[nt], al, bh);
                mma_bf16(acc[nt], ah, bl);
            }
        }
        __syncthreads();   // all reads done before restaging / epilogue overlay
    }

    // --- epilogue: bias + relu -> sH [128][132] f32 (overlays A region)
    float* sH = (float*)(smc + C3_AH);
    {
        int g = lane >> 2, t4 = lane & 3;
        int r0 = w * 16 + g, r1 = r0 + 8;
        #pragma unroll
        for (int nt = 0; nt < 16; nt++) {
            int n = nt * 8 + t4 * 2;
            float b0 = __ldg(&bias[n]), b1 = __ldg(&bias[n + 1]);
            sH[r0 * 132 + n]     = fmaxf(acc[nt][0] + b0, 0.f);
            sH[r0 * 132 + n + 1] = fmaxf(acc[nt][1] + b1, 0.f);
            sH[r1 * 132 + n]     = fmaxf(acc[nt][2] + b0, 0.f);
            sH[r1 * 132 + n + 1] = fmaxf(acc[nt][3] + b1, 0.f);
        }
    }
    __syncthreads();

    // --- GEMM2: [128 x 128] @ [128 x 64] + blin -> out (SIMT, 4x4 tiles)
    {
        const float* sWlin = (const float*)(smc + C3_WL);
        const int rg2 = tid >> 4;   // 0..15
        const int cg2 = tid & 15;   // cols cg2*4
        #pragma unroll 1
        for (int half = 0; half < 2; half++) {
            const int r0 = half * 64 + rg2 * 4;
            float a2[4][4];
            #pragma unroll
            for (int r = 0; r < 4; r++)
                #pragma unroll
                for (int c = 0; c < 4; c++) a2[r][c] = 0.f;
            const float4* h4[4];
            #pragma unroll
            for (int r = 0; r < 4; r++) h4[r] = (const float4*)(sH + (r0 + r) * 132);
            const float* wl2 = sWlin + cg2 * 4;
            #pragma unroll 2
            for (int k4 = 0; k4 < HID / 4; k4++) {
                float4 hv[4];
                #pragma unroll
                for (int r = 0; r < 4; r++) hv[r] = h4[r][k4];
                float hs[4][4];
                #pragma unroll
                for (int r = 0; r < 4; r++) {
                    hs[r][0] = hv[r].x; hs[r][1] = hv[r].y;
                    hs[r][2] = hv[r].z; hs[r][3] = hv[r].w;
                }
                #pragma unroll
                for (int u = 0; u < 4; u++) {
                    float4 w4 = *(const float4*)(wl2 + (k4 * 4 + u) * OUT_D);
                    float ww[4] = {w4.x, w4.y, w4.z, w4.w};
                    #pragma unroll
                    for (int r = 0; r < 4; r++) {
                        float h = hs[r][u];
                        #pragma unroll
                        for (int c = 0; c < 4; c++) a2[r][c] = fmaf(h, ww[c], a2[r][c]);
                    }
                }
            }
            float bl[4];
            #pragma unroll
            for (int c = 0; c < 4; c++) bl[c] = __ldg(blin + cg2 * 4 + c);
            #pragma unroll
            for (int r = 0; r < 4; r++) {
                int lr = r0 + r;
                if (lr < nValid) {
                    float* op = linOut + (size_t)(rowBase + lr) * OUT_D + cg2 * 4;
                    *(float4*)op = make_float4(a2[r][0] + bl[0], a2[r][1] + bl[1],
                                               a2[r][2] + bl[2], a2[r][3] + bl[3]);
                }
            }
        }
    }
}

// ---------------------------------------------------------------------------
// Host launcher
// ---------------------------------------------------------------------------
extern "C" void kernel_launch(void* const* d_in, const int* in_sizes, int n_in,
                              void* d_out, int out_size)
{
    const float* x_user    = (const float*)d_in[0];
    const float* x_movie   = (const float*)d_in[1];
    const int*   edge_user = (const int*)d_in[2];
    const int*   edge_movie= (const int*)d_in[3];
    const float* W1l = (const float*)d_in[4];
    const float* W1r = (const float*)d_in[5];
    const float* b1  = (const float*)d_in[6];
    const float* W2l = (const float*)d_in[7];
    const float* W2r = (const float*)d_in[8];
    const float* b2  = (const float*)d_in[9];
    const float* W3l = (const float*)d_in[10];
    const float* W3r = (const float*)d_in[11];
    const float* b3  = (const float*)d_in[12];
    const float* Wlin1 = (const float*)d_in[13];
    const float* blin1 = (const float*)d_in[14];
    const float* Wlin2 = (const float*)d_in[15];
    const float* blin2 = (const float*)d_in[16];

    float* out = (float*)d_out;
    float* out_user  = out;
    float* out_movie = out + (size_t)N_USER * OUT_D;

    float* scratch = nullptr;
    cudaGetSymbolAddress((void**)&scratch, g_scratch);
    float* agg1   = scratch + OFF_AGG1;
    float* agg2   = scratch + OFF_AGG2;
    float* agg3   = scratch + OFF_AGG3;
    float* degU   = scratch + OFF_DEGU;
    float* degM   = scratch + OFF_DEGM;
    float* userx  = scratch + OFF_USERX;
    float* moviex = scratch + OFF_MOVIEX;

    const int SM_K64   = (2*64*HID  + 64*2*64) * 4;                 // 98304
    const int SM_K64F  = (2*64*HID  + 64*2*64  + HID*OUT_D) * 4;    // 131072

    cudaFuncSetAttribute(update_kernel<64, false, true>,
                         cudaFuncAttributeMaxDynamicSharedMemorySize, SM_K64);
    cudaFuncSetAttribute(update_kernel<64, true, true>,
                         cudaFuncAttributeMaxDynamicSharedMemorySize, SM_K64F);
    cudaFuncSetAttribute(conv3_mma_kernel,
                         cudaFuncAttributeMaxDynamicSharedMemorySize, C3_SMEM);

    static cudaStream_t s2 = nullptr;
    static cudaEvent_t evFork = nullptr, evJoin = nullptr;
    if (!s2) {
        cudaStreamCreateWithFlags(&s2, cudaStreamNonBlocking);
        cudaEventCreateWithFlags(&evFork, cudaEventDisableTiming);
        cudaEventCreateWithFlags(&evJoin, cudaEventDisableTiming);
    }

    cudaMemsetAsync(scratch, 0, (size_t)ZERO_FLOATS * sizeof(float), 0);

    scatter12_kernel<<<(NE * 16) / 256, 256>>>(
        (const float4*)x_movie, (const float4*)x_user,
        edge_movie, edge_user, agg1, agg2, degU, degM);

    const int GU = (N_USER  + 63) / 64;   // 1563
    const int GM = (N_MOVIE + 63) / 64;   // 313
    const int GU3 = (N_USER + 127) / 128; // 782

    // fork: conv1 update (user) on s2, overlapping conv2-update + scatter3
    cudaEventRecord(evFork, 0);
    cudaStreamWaitEvent(s2, evFork, 0);
    update_kernel<64, false, true><<<GU, 256, SM_K64, s2>>>(
        agg1, degU, x_user, W1l, W1r, b1, nullptr, nullptr, userx, nullptr, N_USER);
    cudaEventRecord(evJoin, s2);

    // main: conv2 update (movie) -> moviex + fused out_movie
    update_kernel<64, true, true><<<GM, 256, SM_K64F>>>(
        agg2, degM, x_movie, W2l, W2r, b2, Wlin2, blin2, moviex, out_movie, N_MOVIE);

    // conv3 scatter: moviex -> agg3
    scatter3_kernel<<<(NE * 32) / 256, 256>>>(
        (const float4*)moviex, edge_movie, edge_user, agg3);

    // join: conv3 needs userx from s2
    cudaStreamWaitEvent(0, evJoin, 0);

    // conv3 via mma.sync split-bf16 + fused lin1 -> out_user
    conv3_mma_kernel<<<GU3, 256, C3_SMEM>>>(
        agg3, degU, userx, W3l, W3r, b3, Wlin1, blin1, out_user, N_USER);
}